// round 1
// baseline (speedup 1.0000x reference)
#include <cuda_runtime.h>
#include <cstdint>

#define N_NODES 100000
#define N_EDGES 1600000
#define D 128

// Scratch for support = x @ W  (51.2 MB, static device allocation per harness rules)
__device__ float g_support[(size_t)N_NODES * D];

// ---------------------------------------------------------------------------
// SGEMM: g_support[N,128] = x[N,128] @ w[128,128]
// BM=128, BN=128 (full output width), BK=32, 256 threads, 8x8 microtile.
// ---------------------------------------------------------------------------
__global__ __launch_bounds__(256, 2) void gemm_kernel(const float* __restrict__ x,
                                                      const float* __restrict__ w) {
    __shared__ float xs[128][33];   // pad 33 -> conflict-free column reads
    __shared__ float ws[32][128];

    const int tid = threadIdx.x;
    const int m0  = blockIdx.x * 128;
    const int ty  = tid >> 4;       // 0..15
    const int tx  = tid & 15;       // 0..15

    float acc[8][8];
#pragma unroll
    for (int i = 0; i < 8; i++)
#pragma unroll
        for (int j = 0; j < 8; j++) acc[i][j] = 0.0f;

    for (int kt = 0; kt < 128; kt += 32) {
        // Load x tile: 128 rows x 32 k  (1024 float4, 4 per thread)
#pragma unroll
        for (int i = 0; i < 4; i++) {
            int idx = tid + i * 256;
            int r   = idx >> 3;            // 0..127
            int kk  = (idx & 7) << 2;      // 0,4,...,28
            float4 v = make_float4(0.f, 0.f, 0.f, 0.f);
            if (m0 + r < N_NODES)
                v = *reinterpret_cast<const float4*>(x + (size_t)(m0 + r) * D + kt + kk);
            xs[r][kk + 0] = v.x;
            xs[r][kk + 1] = v.y;
            xs[r][kk + 2] = v.z;
            xs[r][kk + 3] = v.w;
        }
        // Load W tile: 32 k-rows x 128 cols (1024 float4, 4 per thread)
#pragma unroll
        for (int i = 0; i < 4; i++) {
            int idx = tid + i * 256;
            int kr  = idx >> 5;            // 0..31
            int cc  = (idx & 31) << 2;     // 0,4,...,124
            *reinterpret_cast<float4*>(&ws[kr][cc]) =
                *reinterpret_cast<const float4*>(w + (size_t)(kt + kr) * D + cc);
        }
        __syncthreads();

#pragma unroll
        for (int k = 0; k < 32; k++) {
            float a[8], b[8];
#pragma unroll
            for (int i = 0; i < 8; i++) a[i] = xs[ty * 8 + i][k];
#pragma unroll
            for (int j = 0; j < 8; j++) b[j] = ws[k][tx * 8 + j];
#pragma unroll
            for (int i = 0; i < 8; i++)
#pragma unroll
                for (int j = 0; j < 8; j++) acc[i][j] = fmaf(a[i], b[j], acc[i][j]);
        }
        __syncthreads();
    }

    // Store 8x8 microtile as 2 float4 per row
#pragma unroll
    for (int i = 0; i < 8; i++) {
        int r = m0 + ty * 8 + i;
        if (r < N_NODES) {
            float4 v0 = make_float4(acc[i][0], acc[i][1], acc[i][2], acc[i][3]);
            float4 v1 = make_float4(acc[i][4], acc[i][5], acc[i][6], acc[i][7]);
            float* dst = g_support + (size_t)r * D + tx * 8;
            *reinterpret_cast<float4*>(dst)     = v0;
            *reinterpret_cast<float4*>(dst + 4) = v1;
        }
    }
}

// ---------------------------------------------------------------------------
// Scatter: out[row[e]] += ew[e] * g_support[col[e]]
// One warp per edge: each lane handles 4 contiguous floats via one float4
// gather + one red.global.add.v4.f32 (vector reduction, sm_90+).
// ---------------------------------------------------------------------------
__global__ __launch_bounds__(256) void scatter_kernel(const int* __restrict__ row,
                                                      const int* __restrict__ col,
                                                      const float* __restrict__ ew,
                                                      float* __restrict__ out) {
    const int64_t warp = ((int64_t)blockIdx.x * blockDim.x + threadIdx.x) >> 5;
    const int lane = threadIdx.x & 31;
    if (warp >= N_EDGES) return;

    const int   r = __ldg(row + warp);
    const int   c = __ldg(col + warp);
    const float w = __ldg(ew + warp);

    const float4 s = *reinterpret_cast<const float4*>(g_support + (size_t)c * D + lane * 4);
    const float mx = s.x * w, my = s.y * w, mz = s.z * w, mw = s.w * w;

    float* dst = out + (size_t)r * D + lane * 4;
    asm volatile("red.global.add.v4.f32 [%0], {%1, %2, %3, %4};"
                 :: "l"(dst), "f"(mx), "f"(my), "f"(mz), "f"(mw)
                 : "memory");
}

// ---------------------------------------------------------------------------
// Launch
// ---------------------------------------------------------------------------
extern "C" void kernel_launch(void* const* d_in, const int* in_sizes, int n_in,
                              void* d_out, int out_size) {
    const float* x    = (const float*)d_in[0];   // [N_NODES, 128]
    const int*   row  = (const int*)  d_in[1];   // [N_EDGES]
    const int*   col  = (const int*)  d_in[2];   // [N_EDGES]
    const float* ew   = (const float*)d_in[3];   // [N_EDGES]
    const float* wmat = (const float*)d_in[4];   // [128, 128]
    float*       out  = (float*)d_out;           // [N_NODES, 128]

    (void)in_sizes; (void)n_in; (void)out_size;

    // out is poisoned by the harness; zero it (async, graph-capturable)
    cudaMemsetAsync(out, 0, (size_t)N_NODES * D * sizeof(float), 0);

    // support = x @ W
    gemm_kernel<<<(N_NODES + 127) / 128, 256>>>(x, wmat);

    // out[row] += ew * support[col]   (8 warps/block, 1 edge/warp)
    const int warps_per_block = 256 / 32;
    const int blocks = (N_EDGES + warps_per_block - 1) / warps_per_block;
    scatter_kernel<<<blocks, 256>>>(row, col, ew, out);
}

// round 2
// speedup vs baseline: 1.2056x; 1.2056x over previous
#include <cuda_runtime.h>
#include <cstdint>

#define N_NODES 100000
#define N_EDGES 1600000
#define D 128

// Scratch for support = x @ W  (51.2 MB, static device allocation per harness rules)
__device__ float g_support[(size_t)N_NODES * D];

// ---------------------------------------------------------------------------
// SGEMM: g_support[N,128] = x[N,128] @ w[128,128]
// BM=128, BN=128 (full output width), BK=32, 256 threads, 8x8 microtile.
// Epilogue also zeroes out[] for the same rows (replaces cudaMemsetAsync).
// ---------------------------------------------------------------------------
__global__ __launch_bounds__(256, 2) void gemm_kernel(const float* __restrict__ x,
                                                      const float* __restrict__ w,
                                                      float* __restrict__ out) {
    __shared__ float xs[128][33];   // pad 33 -> conflict-free column reads
    __shared__ float ws[32][128];

    const int tid = threadIdx.x;
    const int m0  = blockIdx.x * 128;
    const int ty  = tid >> 4;       // 0..15
    const int tx  = tid & 15;       // 0..15

    float acc[8][8];
#pragma unroll
    for (int i = 0; i < 8; i++)
#pragma unroll
        for (int j = 0; j < 8; j++) acc[i][j] = 0.0f;

    for (int kt = 0; kt < 128; kt += 32) {
        // Load x tile: 128 rows x 32 k  (1024 float4, 4 per thread)
#pragma unroll
        for (int i = 0; i < 4; i++) {
            int idx = tid + i * 256;
            int r   = idx >> 3;            // 0..127
            int kk  = (idx & 7) << 2;      // 0,4,...,28
            float4 v = make_float4(0.f, 0.f, 0.f, 0.f);
            if (m0 + r < N_NODES)
                v = *reinterpret_cast<const float4*>(x + (size_t)(m0 + r) * D + kt + kk);
            xs[r][kk + 0] = v.x;
            xs[r][kk + 1] = v.y;
            xs[r][kk + 2] = v.z;
            xs[r][kk + 3] = v.w;
        }
        // Load W tile: 32 k-rows x 128 cols (1024 float4, 4 per thread)
#pragma unroll
        for (int i = 0; i < 4; i++) {
            int idx = tid + i * 256;
            int kr  = idx >> 5;            // 0..31
            int cc  = (idx & 31) << 2;     // 0,4,...,124
            *reinterpret_cast<float4*>(&ws[kr][cc]) =
                *reinterpret_cast<const float4*>(w + (size_t)(kt + kr) * D + cc);
        }
        __syncthreads();

#pragma unroll
        for (int k = 0; k < 32; k++) {
            float a[8], b[8];
#pragma unroll
            for (int i = 0; i < 8; i++) a[i] = xs[ty * 8 + i][k];
#pragma unroll
            for (int j = 0; j < 8; j++) b[j] = ws[k][tx * 8 + j];
#pragma unroll
            for (int i = 0; i < 8; i++)
#pragma unroll
                for (int j = 0; j < 8; j++) acc[i][j] = fmaf(a[i], b[j], acc[i][j]);
        }
        __syncthreads();
    }

    // Store 8x8 microtile as 2 float4 per row; also zero the matching out region
    const float4 z = make_float4(0.f, 0.f, 0.f, 0.f);
#pragma unroll
    for (int i = 0; i < 8; i++) {
        int r = m0 + ty * 8 + i;
        if (r < N_NODES) {
            float4 v0 = make_float4(acc[i][0], acc[i][1], acc[i][2], acc[i][3]);
            float4 v1 = make_float4(acc[i][4], acc[i][5], acc[i][6], acc[i][7]);
            float* dst = g_support + (size_t)r * D + tx * 8;
            *reinterpret_cast<float4*>(dst)     = v0;
            *reinterpret_cast<float4*>(dst + 4) = v1;
            float* odst = out + (size_t)r * D + tx * 8;
            *reinterpret_cast<float4*>(odst)     = z;
            *reinterpret_cast<float4*>(odst + 4) = z;
        }
    }
}

// ---------------------------------------------------------------------------
// Scatter: out[row[e]] += ew[e] * g_support[col[e]]
// Persistent grid-stride, 4 edges per warp-iteration.
// Metadata (row/col/ew) loaded as one int4/float4 broadcast per 4 edges.
// 4 independent float4 gathers batched before 4 red.global.add.v4.f32.
// ---------------------------------------------------------------------------
#define UNROLL_E 4

__global__ __launch_bounds__(256) void scatter_kernel(const int* __restrict__ row,
                                                      const int* __restrict__ col,
                                                      const float* __restrict__ ew,
                                                      float* __restrict__ out) {
    const int lane = threadIdx.x & 31;
    const int warp_global = (blockIdx.x * blockDim.x + threadIdx.x) >> 5;
    const int nwarps = (gridDim.x * blockDim.x) >> 5;

    const int lane_off = lane * 4;

    for (int64_t e0 = (int64_t)warp_global * UNROLL_E; e0 < N_EDGES;
         e0 += (int64_t)nwarps * UNROLL_E) {
        // N_EDGES % 4 == 0 and stride % 4 == 0 -> e0..e0+3 always valid
        const int4   r4 = *reinterpret_cast<const int4*>(row + e0);
        const int4   c4 = *reinterpret_cast<const int4*>(col + e0);
        const float4 w4 = *reinterpret_cast<const float4*>(ew + e0);

        const int r[UNROLL_E] = {r4.x, r4.y, r4.z, r4.w};
        const int c[UNROLL_E] = {c4.x, c4.y, c4.z, c4.w};
        const float wv[UNROLL_E] = {w4.x, w4.y, w4.z, w4.w};

        float4 s[UNROLL_E];
#pragma unroll
        for (int j = 0; j < UNROLL_E; j++)
            s[j] = *reinterpret_cast<const float4*>(g_support + (size_t)c[j] * D + lane_off);

#pragma unroll
        for (int j = 0; j < UNROLL_E; j++) {
            const float mx = s[j].x * wv[j], my = s[j].y * wv[j];
            const float mz = s[j].z * wv[j], mw = s[j].w * wv[j];
            float* dst = out + (size_t)r[j] * D + lane_off;
            asm volatile("red.global.add.v4.f32 [%0], {%1, %2, %3, %4};"
                         :: "l"(dst), "f"(mx), "f"(my), "f"(mz), "f"(mw)
                         : "memory");
        }
    }
}

// ---------------------------------------------------------------------------
// Launch
// ---------------------------------------------------------------------------
extern "C" void kernel_launch(void* const* d_in, const int* in_sizes, int n_in,
                              void* d_out, int out_size) {
    const float* x    = (const float*)d_in[0];   // [N_NODES, 128]
    const int*   row  = (const int*)  d_in[1];   // [N_EDGES]
    const int*   col  = (const int*)  d_in[2];   // [N_EDGES]
    const float* ew   = (const float*)d_in[3];   // [N_EDGES]
    const float* wmat = (const float*)d_in[4];   // [128, 128]
    float*       out  = (float*)d_out;           // [N_NODES, 128]

    (void)in_sizes; (void)n_in; (void)out_size;

    // support = x @ W  (also zeroes out[])
    gemm_kernel<<<(N_NODES + 127) / 128, 256>>>(x, wmat, out);

    // out[row] += ew * support[col]   (persistent, 4 edges/warp-iter)
    const int blocks = 148 * 16;   // persistent-ish grid, grid-stride loop
    scatter_kernel<<<blocks, 256>>>(row, col, ew, out);
}